// round 2
// baseline (speedup 1.0000x reference)
#include <cuda_runtime.h>
#include <cuda_bf16.h>
#include <math.h>

// Problem constants
#define BB 2
#define CC 64
#define HH 192
#define WW 192
#define HP 194   // padded
#define NTAP 9

// ---------------- scratch buffers (static device memory; no allocation) -----
__device__ float g_frpad[BB * CC * HP * HP];            // padded f_r
__device__ float g_offset[BB * 18 * HH * WW];           // pconv output
__device__ float g_x[BB * CC * HH * WW];                // deform conv output
__device__ float g_y[BB * CC * HH * WW];                // running feature map
__device__ float g_t1[BB * CC * 190 * 190];             // resblock intermediate

// ---------------- pad kernel: f_r -> g_frpad (pad=1, zero) -----------------
__global__ void pad_kernel(const float* __restrict__ src, float* __restrict__ dst) {
    int idx = blockIdx.x * blockDim.x + threadIdx.x;
    int total = BB * CC * HP * HP;
    if (idx >= total) return;
    int c2 = idx % HP;
    int r2 = (idx / HP) % HP;
    int bc = idx / (HP * HP);
    float v = 0.f;
    if (r2 >= 1 && r2 <= HH && c2 >= 1 && c2 <= WW) {
        v = src[(size_t)bc * HH * WW + (r2 - 1) * WW + (c2 - 1)];
    }
    dst[idx] = v;
}

// ---------------- generic 3x3 conv ------------------------------------------
// Tile: 16x16 output pixels per block, 256 threads, CH=8 input-channel chunks.
// Weights staged in SMEM as [ci_local][k][co] -> broadcast float4 loads.
template<int CIN, int COUT, int PADV, bool HAS_IN2>
__global__ void __launch_bounds__(256, 1)
conv3x3_kernel(const float* __restrict__ inA,
               const float* __restrict__ inB,     // second 64 channels if HAS_IN2
               const float* __restrict__ w,       // (COUT, CIN, 3, 3)
               const float* __restrict__ bias,    // may be null
               const float* __restrict__ res,     // may be null (B,COUT,Hout,Wout)
               float* __restrict__ out,
               int Hin, int Win, int Hout, int Wout)
{
    constexpr int CH = 8;
    constexpr int COUT_P = (COUT + 3) & ~3;
    __shared__ __align__(16) float sIn[CH][18][18];
    __shared__ __align__(16) float sW[CH * 9 * COUT_P];

    const int b   = blockIdx.z;
    const int ty0 = blockIdx.y * 16;
    const int tx0 = blockIdx.x * 16;
    const int tid = threadIdx.x;
    const int py = tid >> 4, px = tid & 15;
    const int oy = ty0 + py, ox = tx0 + px;

    float acc[COUT_P];
#pragma unroll
    for (int i = 0; i < COUT_P; i++) acc[i] = 0.f;

    const int cstride = HAS_IN2 ? 64 : CIN;

    for (int c0 = 0; c0 < CIN; c0 += CH) {
        // stage input tile (18x18 per channel)
        for (int idx = tid; idx < CH * 18 * 18; idx += 256) {
            int c   = idx / (18 * 18);
            int rem = idx % (18 * 18);
            int r = rem / 18, cc = rem % 18;
            int iy = ty0 - PADV + r;
            int ix = tx0 - PADV + cc;
            float v = 0.f;
            if (iy >= 0 && iy < Hin && ix >= 0 && ix < Win) {
                int ci = c0 + c;
                const float* src = inA;
                int cl = ci;
                if (HAS_IN2 && ci >= 64) { src = inB; cl = ci - 64; }
                v = src[(((size_t)b * cstride + cl) * Hin + iy) * Win + ix];
            }
            sIn[c][r][cc] = v;
        }
        // stage weights [ci_l][k][co]
        for (int idx = tid; idx < CH * 9 * COUT_P; idx += 256) {
            int co = idx % COUT_P;
            int ck = idx / COUT_P;
            int ci_l = ck / 9, k = ck % 9;
            float v = 0.f;
            if (co < COUT) v = w[((size_t)co * CIN + (c0 + ci_l)) * 9 + k];
            sW[idx] = v;
        }
        __syncthreads();

        for (int ci = 0; ci < CH; ci++) {
#pragma unroll
            for (int ky = 0; ky < 3; ky++) {
#pragma unroll
                for (int kx = 0; kx < 3; kx++) {
                    float xv = sIn[ci][py + ky][px + kx];
                    const float4* wp = reinterpret_cast<const float4*>(
                        &sW[(ci * 9 + ky * 3 + kx) * COUT_P]);
#pragma unroll
                    for (int j = 0; j < COUT_P / 4; j++) {
                        float4 w4 = wp[j];
                        acc[4 * j + 0] = fmaf(w4.x, xv, acc[4 * j + 0]);
                        acc[4 * j + 1] = fmaf(w4.y, xv, acc[4 * j + 1]);
                        acc[4 * j + 2] = fmaf(w4.z, xv, acc[4 * j + 2]);
                        acc[4 * j + 3] = fmaf(w4.w, xv, acc[4 * j + 3]);
                    }
                }
            }
        }
        __syncthreads();
    }

    if (oy < Hout && ox < Wout) {
        size_t obase = (size_t)b * COUT * Hout * Wout + (size_t)oy * Wout + ox;
        size_t cs = (size_t)Hout * Wout;
#pragma unroll
        for (int co = 0; co < COUT; co++) {
            float v = acc[co];
            if (bias) v += bias[co];
            if (res)  v += res[obase + co * cs];
            out[obase + co * cs] = v;
        }
    }
}

// ---------------- deformable conv -------------------------------------------
__global__ void __launch_bounds__(256, 1)
deform_kernel(const float* __restrict__ xpad,    // (B,64,194,194)
              const float* __restrict__ offset,  // (B,18,192,192)
              const float* __restrict__ wdc,     // (64,64,3,3)
              float* __restrict__ out)           // (B,64,192,192)
{
    __shared__ __align__(16) float sW[64 * 64];  // [ci][co] for current tap

    const int b = blockIdx.z;
    const int ty0 = blockIdx.y * 16, tx0 = blockIdx.x * 16;
    const int tid = threadIdx.x;
    const int py = tid >> 4, px = tid & 15;
    const int i = ty0 + py, j = tx0 + px;   // 192 % 16 == 0, always in range

    float acc[64];
#pragma unroll
    for (int c = 0; c < 64; c++) acc[c] = 0.f;

    for (int n = 0; n < NTAP; n++) {
        __syncthreads();
        for (int idx = tid; idx < 4096; idx += 256) {
            int ci = idx >> 6, co = idx & 63;
            sW[idx] = wdc[((size_t)co * 64 + ci) * 9 + n];
        }
        __syncthreads();

        int dr = n / 3 - 1, dc = n % 3 - 1;
        float offr = offset[(((size_t)b * 18 + n) * HH + i) * WW + j];
        float offc = offset[(((size_t)b * 18 + 9 + n) * HH + i) * WW + j];
        float p_r = (float)(i + 1 + dr) + offr;
        float p_c = (float)(j + 1 + dc) + offc;
        float pr = fminf(fmaxf(p_r, 0.f), 193.f);
        float pc = fminf(fmaxf(p_c, 0.f), 193.f);
        float fr = floorf(p_r), fc = floorf(p_c);
        float qr0 = fminf(fmaxf(fr,       0.f), 193.f);
        float qc0 = fminf(fmaxf(fc,       0.f), 193.f);
        float qr1 = fminf(fmaxf(fr + 1.f, 0.f), 193.f);
        float qc1 = fminf(fmaxf(fc + 1.f, 0.f), 193.f);
        float glt = (1.f + (qr0 - pr)) * (1.f + (qc0 - pc));
        float grb = (1.f - (qr1 - pr)) * (1.f - (qc1 - pc));
        float glb = (1.f + (qr0 - pr)) * (1.f - (qc1 - pc));
        float grt = (1.f - (qr1 - pr)) * (1.f + (qc0 - pc));
        int i00 = (int)qr0 * HP + (int)qc0;
        int i11 = (int)qr1 * HP + (int)qc1;
        int i01 = (int)qr0 * HP + (int)qc1;
        int i10 = (int)qr1 * HP + (int)qc0;

        const float* xb = xpad + (size_t)b * 64 * HP * HP;
        for (int ci = 0; ci < 64; ci++) {
            const float* xc = xb + (size_t)ci * HP * HP;
            float xo = glt * xc[i00] + grb * xc[i11]
                     + glb * xc[i01] + grt * xc[i10];
            const float4* wp = reinterpret_cast<const float4*>(&sW[ci * 64]);
#pragma unroll
            for (int jj = 0; jj < 16; jj++) {
                float4 w4 = wp[jj];
                acc[4 * jj + 0] = fmaf(w4.x, xo, acc[4 * jj + 0]);
                acc[4 * jj + 1] = fmaf(w4.y, xo, acc[4 * jj + 1]);
                acc[4 * jj + 2] = fmaf(w4.z, xo, acc[4 * jj + 2]);
                acc[4 * jj + 3] = fmaf(w4.w, xo, acc[4 * jj + 3]);
            }
        }
    }

    size_t obase = (size_t)b * 64 * HH * WW + (size_t)i * WW + j;
#pragma unroll
    for (int co = 0; co < 64; co++)
        out[obase + (size_t)co * HH * WW] = acc[co];
}

// ---------------- GDN + celu (in place) --------------------------------------
// x <- celu( x / sqrt(beta + gamma @ x^2) ), per-pixel 1x1 contraction.
__global__ void __launch_bounds__(256, 1)
gdn_celu_kernel(float* __restrict__ x, const float* __restrict__ beta,
                const float* __restrict__ gamma, int HWp)
{
    __shared__ __align__(16) float sG[64 * 64];  // sG[ci*64+co] = gamma[co][ci]
    __shared__ float sB[64];
    const int tid = threadIdx.x;
    for (int idx = tid; idx < 4096; idx += 256) {
        int co = idx & 63, ci = idx >> 6;
        sG[idx] = gamma[co * 64 + ci];
    }
    if (tid < 64) sB[tid] = beta[tid];
    __syncthreads();

    int p = blockIdx.x * 256 + tid;
    if (p >= BB * HWp) return;
    int b = p / HWp, hw = p % HWp;
    float* base = x + (size_t)b * 64 * HWp + hw;

    float nrm[64];
#pragma unroll
    for (int co = 0; co < 64; co++) nrm[co] = sB[co];

    for (int ci = 0; ci < 64; ci++) {
        float v = base[(size_t)ci * HWp];
        float sq = v * v;
        const float4* gp = reinterpret_cast<const float4*>(&sG[ci * 64]);
#pragma unroll
        for (int jj = 0; jj < 16; jj++) {
            float4 g4 = gp[jj];
            nrm[4 * jj + 0] = fmaf(g4.x, sq, nrm[4 * jj + 0]);
            nrm[4 * jj + 1] = fmaf(g4.y, sq, nrm[4 * jj + 1]);
            nrm[4 * jj + 2] = fmaf(g4.z, sq, nrm[4 * jj + 2]);
            nrm[4 * jj + 3] = fmaf(g4.w, sq, nrm[4 * jj + 3]);
        }
    }
#pragma unroll
    for (int co = 0; co < 64; co++) {
        float v = base[(size_t)co * HWp];
        float t = v * rsqrtf(nrm[co]);
        base[(size_t)co * HWp] = (t > 0.f) ? t : expm1f(t);
    }
}

// ---------------- final add: out = y + x -------------------------------------
__global__ void add_kernel(const float* __restrict__ a, const float* __restrict__ b,
                           float* __restrict__ out, int n)
{
    int i = blockIdx.x * blockDim.x + threadIdx.x;
    if (i < n) out[i] = a[i] + b[i];
}

// ---------------- launcher ---------------------------------------------------
extern "C" void kernel_launch(void* const* d_in, const int* in_sizes, int n_in,
                              void* d_out, int out_size)
{
    const float* f_r     = (const float*)d_in[0];
    const float* m_t     = (const float*)d_in[1];
    const float* w_pconv = (const float*)d_in[2];
    const float* b_pconv = (const float*)d_in[3];
    const float* w_dc    = (const float*)d_in[4];
    const float* w_cat   = (const float*)d_in[5];
    const float* b_cat   = (const float*)d_in[6];
    const float* rb_w1   = (const float*)d_in[7];
    const float* rb_w2   = (const float*)d_in[8];
    const float* rb_beta = (const float*)d_in[9];
    const float* rb_gamma= (const float*)d_in[10];
    float* out = (float*)d_out;

    float *frpad, *offs, *xbuf, *ybuf, *t1;
    cudaGetSymbolAddress((void**)&frpad, g_frpad);
    cudaGetSymbolAddress((void**)&offs,  g_offset);
    cudaGetSymbolAddress((void**)&xbuf,  g_x);
    cudaGetSymbolAddress((void**)&ybuf,  g_y);
    cudaGetSymbolAddress((void**)&t1,    g_t1);

    // 1. pad f_r
    {
        int total = BB * CC * HP * HP;
        pad_kernel<<<(total + 255) / 256, 256>>>(f_r, frpad);
    }
    // 2. offset = pconv(m_t), pad 1, 64->18
    {
        dim3 grid(12, 12, BB);
        conv3x3_kernel<64, 18, 1, false><<<grid, 256>>>(
            m_t, nullptr, w_pconv, b_pconv, nullptr, offs, HH, WW, HH, WW);
    }
    // 3. x = deform_conv(f_r, offset, w_dc)
    {
        dim3 grid(12, 12, BB);
        deform_kernel<<<grid, 256>>>(frpad, offs, w_dc, xbuf);
    }
    // 4. y = conv(cat[x, f_r]), pad 1, 128->64
    {
        dim3 grid(12, 12, BB);
        conv3x3_kernel<128, 64, 1, true><<<grid, 256>>>(
            xbuf, f_r, w_cat, b_cat, nullptr, ybuf, HH, WW, HH, WW);
    }
    // 5. resblocks
    for (int l = 0; l < 3; l++) {
        const float* w1 = rb_w1 + (size_t)l * 64 * 64 * 9;
        const float* w2 = rb_w2 + (size_t)l * 64 * 64 * 9;
        const float* bt = rb_beta + (size_t)l * 64;
        const float* gm = rb_gamma + (size_t)l * 64 * 64;
        // conv1: pad 0, 192 -> 190
        {
            dim3 grid(12, 12, BB);  // ceil(190/16)=12
            conv3x3_kernel<64, 64, 0, false><<<grid, 256>>>(
                ybuf, nullptr, w1, nullptr, nullptr, t1, HH, WW, 190, 190);
        }
        // gdn + celu in place on t1
        {
            int HWp = 190 * 190;
            int total = BB * HWp;
            gdn_celu_kernel<<<(total + 255) / 256, 256>>>(t1, bt, gm, HWp);
        }
        // conv2: pad 2, 190 -> 192, + residual y (in place into y)
        {
            dim3 grid(12, 12, BB);
            conv3x3_kernel<64, 64, 2, false><<<grid, 256>>>(
                t1, nullptr, w2, nullptr, ybuf, ybuf, 190, 190, HH, WW);
        }
    }
    // 6. out = y + x
    {
        int n = BB * CC * HH * WW;
        add_kernel<<<(n + 255) / 256, 256>>>(ybuf, xbuf, out, n);
    }
}

// round 3
// speedup vs baseline: 1.5430x; 1.5430x over previous
#include <cuda_runtime.h>
#include <cuda_bf16.h>
#include <math.h>

// Problem constants
#define BB 2
#define CC 64
#define HH 192
#define WW 192
#define HP 194   // padded
#define NTAP 9

typedef unsigned long long u64;

// ---------------- f32x2 packed helpers --------------------------------------
__device__ __forceinline__ u64 dup2(float x) {
    u64 r; asm("mov.b64 %0, {%1,%1};" : "=l"(r) : "f"(x)); return r;
}
__device__ __forceinline__ u64 pk2(float lo, float hi) {
    u64 r; asm("mov.b64 %0, {%1,%2};" : "=l"(r) : "f"(lo), "f"(hi)); return r;
}
__device__ __forceinline__ void fma2(u64 &d, u64 a, u64 b) {
    asm("fma.rn.f32x2 %0, %1, %2, %0;" : "+l"(d) : "l"(a), "l"(b));
}
__device__ __forceinline__ float2 unpk(u64 v) {
    float2 f; asm("mov.b64 {%0,%1}, %2;" : "=f"(f.x), "=f"(f.y) : "l"(v)); return f;
}

// ---------------- scratch buffers (static device memory; no allocation) -----
__device__ float g_frpad[BB * CC * HP * HP];
__device__ float g_offset[BB * 18 * HH * WW];
__device__ float g_x[BB * CC * HH * WW];
__device__ float g_y[BB * CC * HH * WW];
__device__ float g_t1[BB * CC * 190 * 190];

// ---------------- pad kernel -------------------------------------------------
__global__ void pad_kernel(const float* __restrict__ src, float* __restrict__ dst) {
    int idx = blockIdx.x * blockDim.x + threadIdx.x;
    int total = BB * CC * HP * HP;
    if (idx >= total) return;
    int c2 = idx % HP;
    int r2 = (idx / HP) % HP;
    int bc = idx / (HP * HP);
    float v = 0.f;
    if (r2 >= 1 && r2 <= HH && c2 >= 1 && c2 <= WW)
        v = src[(size_t)bc * HH * WW + (r2 - 1) * WW + (c2 - 1)];
    dst[idx] = v;
}

// ---------------- old generic 3x3 conv (kept for pconv, COUT=18) ------------
template<int CIN, int COUT, int PADV, bool HAS_IN2>
__global__ void __launch_bounds__(256, 1)
conv3x3_kernel(const float* __restrict__ inA, const float* __restrict__ inB,
               const float* __restrict__ w, const float* __restrict__ bias,
               const float* __restrict__ res, float* __restrict__ out,
               int Hin, int Win, int Hout, int Wout)
{
    constexpr int CH = 8;
    constexpr int COUT_P = (COUT + 3) & ~3;
    __shared__ __align__(16) float sIn[CH][18][18];
    __shared__ __align__(16) float sW[CH * 9 * COUT_P];

    const int b   = blockIdx.z;
    const int ty0 = blockIdx.y * 16;
    const int tx0 = blockIdx.x * 16;
    const int tid = threadIdx.x;
    const int py = tid >> 4, px = tid & 15;
    const int oy = ty0 + py, ox = tx0 + px;

    float acc[COUT_P];
#pragma unroll
    for (int i = 0; i < COUT_P; i++) acc[i] = 0.f;

    const int cstride = HAS_IN2 ? 64 : CIN;

    for (int c0 = 0; c0 < CIN; c0 += CH) {
        for (int idx = tid; idx < CH * 18 * 18; idx += 256) {
            int c   = idx / (18 * 18);
            int rem = idx % (18 * 18);
            int r = rem / 18, cc = rem % 18;
            int iy = ty0 - PADV + r;
            int ix = tx0 - PADV + cc;
            float v = 0.f;
            if (iy >= 0 && iy < Hin && ix >= 0 && ix < Win) {
                int ci = c0 + c;
                const float* src = inA;
                int cl = ci;
                if (HAS_IN2 && ci >= 64) { src = inB; cl = ci - 64; }
                v = src[(((size_t)b * cstride + cl) * Hin + iy) * Win + ix];
            }
            sIn[c][r][cc] = v;
        }
        for (int idx = tid; idx < CH * 9 * COUT_P; idx += 256) {
            int co = idx % COUT_P;
            int ck = idx / COUT_P;
            int ci_l = ck / 9, k = ck % 9;
            float v = 0.f;
            if (co < COUT) v = w[((size_t)co * CIN + (c0 + ci_l)) * 9 + k];
            sW[idx] = v;
        }
        __syncthreads();

        for (int ci = 0; ci < CH; ci++) {
#pragma unroll
            for (int ky = 0; ky < 3; ky++) {
#pragma unroll
                for (int kx = 0; kx < 3; kx++) {
                    float xv = sIn[ci][py + ky][px + kx];
                    const float4* wp = reinterpret_cast<const float4*>(
                        &sW[(ci * 9 + ky * 3 + kx) * COUT_P]);
#pragma unroll
                    for (int j = 0; j < COUT_P / 4; j++) {
                        float4 w4 = wp[j];
                        acc[4 * j + 0] = fmaf(w4.x, xv, acc[4 * j + 0]);
                        acc[4 * j + 1] = fmaf(w4.y, xv, acc[4 * j + 1]);
                        acc[4 * j + 2] = fmaf(w4.z, xv, acc[4 * j + 2]);
                        acc[4 * j + 3] = fmaf(w4.w, xv, acc[4 * j + 3]);
                    }
                }
            }
        }
        __syncthreads();
    }

    if (oy < Hout && ox < Wout) {
        size_t obase = (size_t)b * COUT * Hout * Wout + (size_t)oy * Wout + ox;
        size_t cs = (size_t)Hout * Wout;
#pragma unroll
        for (int co = 0; co < COUT; co++) {
            float v = acc[co];
            if (bias) v += bias[co];
            if (res)  v += res[obase + co * cs];
            out[obase + co * cs] = v;
        }
    }
}

// ---------------- FFMA2 3x3 conv, COUT=64 ------------------------------------
// Block = 256 threads = 2 cout-halves x 128 threads.
// Each thread: 2x2 pixel quad x 32 output channels, channel-packed f32x2.
// Tile: 16 rows x 32 cols of output per block.
template<int CIN, int PADV, bool HAS_IN2>
__global__ void __launch_bounds__(256, 1)
conv3x3_f2_kernel(const float* __restrict__ inA, const float* __restrict__ inB,
                  const float* __restrict__ w, const float* __restrict__ bias,
                  const float* __restrict__ res, float* __restrict__ out,
                  int Hin, int Win, int Hout, int Wout)
{
    constexpr int CH = 8;
    __shared__ __align__(16) float sIn[CH][18][36];   // rows 18, padded cols 36 (34 used)
    __shared__ __align__(16) float sW[CH][9][64];     // [ci][tap][co] (co pairs contiguous)

    const int b   = blockIdx.z;
    const int ty0 = blockIdx.y * 16;
    const int tx0 = blockIdx.x * 32;
    const int tid = threadIdx.x;
    const int g   = tid >> 7;          // cout half: co base = g*32
    const int t   = tid & 127;
    const int qy  = t >> 4;            // 0..7   (output row pair)
    const int qx  = t & 15;            // 0..15  (output col pair)

    u64 acc[4][16];
#pragma unroll
    for (int p = 0; p < 4; p++)
#pragma unroll
        for (int j = 0; j < 16; j++) acc[p][j] = 0ull;

    const int cstride = HAS_IN2 ? 64 : CIN;

    for (int c0 = 0; c0 < CIN; c0 += CH) {
        // stage input tile
        for (int idx = tid; idx < CH * 18 * 36; idx += 256) {
            int c   = idx / 648;
            int rem = idx % 648;
            int r = rem / 36, cc = rem % 36;
            int iy = ty0 - PADV + r;
            int ix = tx0 - PADV + cc;
            float v = 0.f;
            if (cc < 34 && iy >= 0 && iy < Hin && ix >= 0 && ix < Win) {
                int ci = c0 + c;
                const float* src = inA;
                int cl = ci;
                if (HAS_IN2 && ci >= 64) { src = inB; cl = ci - 64; }
                v = src[(((size_t)b * cstride + cl) * Hin + iy) * Win + ix];
            }
            (&sIn[0][0][0])[idx] = v;
        }
        // stage weights [ci][tap][co]
        for (int idx = tid; idx < CH * 9 * 64; idx += 256) {
            int co = idx & 63;
            int ck = idx >> 6;
            int ci = ck / 9, k = ck % 9;
            (&sW[0][0][0])[idx] = w[((size_t)co * CIN + (c0 + ci)) * 9 + k];
        }
        __syncthreads();

#pragma unroll 1
        for (int ci = 0; ci < CH; ci++) {
            // 4 input rows x 4 scalars each, pre-duplicated into f32x2
            u64 d[4][4];
#pragma unroll
            for (int r = 0; r < 4; r++) {
                const float2* ip = reinterpret_cast<const float2*>(&sIn[ci][2 * qy + r][2 * qx]);
                float2 a = ip[0], bb = ip[1];
                d[r][0] = dup2(a.x); d[r][1] = dup2(a.y);
                d[r][2] = dup2(bb.x); d[r][3] = dup2(bb.y);
            }
#pragma unroll
            for (int ky = 0; ky < 3; ky++) {
#pragma unroll
                for (int kx = 0; kx < 3; kx++) {
                    u64 xv0 = d[ky + 0][kx + 0];
                    u64 xv1 = d[ky + 0][kx + 1];
                    u64 xv2 = d[ky + 1][kx + 0];
                    u64 xv3 = d[ky + 1][kx + 1];
                    const ulonglong2* wp = reinterpret_cast<const ulonglong2*>(
                        &sW[ci][ky * 3 + kx][g * 32]);
#pragma unroll
                    for (int j = 0; j < 8; j++) {
                        ulonglong2 q = wp[j];
                        fma2(acc[0][2 * j], xv0, q.x); fma2(acc[0][2 * j + 1], xv0, q.y);
                        fma2(acc[1][2 * j], xv1, q.x); fma2(acc[1][2 * j + 1], xv1, q.y);
                        fma2(acc[2][2 * j], xv2, q.x); fma2(acc[2][2 * j + 1], xv2, q.y);
                        fma2(acc[3][2 * j], xv3, q.x); fma2(acc[3][2 * j + 1], xv3, q.y);
                    }
                }
            }
        }
        __syncthreads();
    }

    // store
    size_t cs = (size_t)Hout * Wout;
#pragma unroll
    for (int pr = 0; pr < 2; pr++) {
#pragma unroll
        for (int pc = 0; pc < 2; pc++) {
            int oy = ty0 + 2 * qy + pr;
            int ox = tx0 + 2 * qx + pc;
            if (oy < Hout && ox < Wout) {
                size_t base = (size_t)b * 64 * cs + (size_t)oy * Wout + ox;
                u64* ac = acc[pr * 2 + pc];
#pragma unroll
                for (int j = 0; j < 16; j++) {
                    float2 v = unpk(ac[j]);
                    int co = g * 32 + 2 * j;
                    float o0 = v.x, o1 = v.y;
                    if (bias) { o0 += bias[co]; o1 += bias[co + 1]; }
                    if (res)  { o0 += res[base + (size_t)co * cs];
                                o1 += res[base + (size_t)(co + 1) * cs]; }
                    out[base + (size_t)co * cs]       = o0;
                    out[base + (size_t)(co + 1) * cs] = o1;
                }
            }
        }
    }
}

// ---------------- deformable conv, FFMA2 -------------------------------------
// Block 256 threads, tile 16 rows x 32 cols; each thread: 2 horizontal pixels,
// all 64 couts channel-packed (32 f32x2 pairs per pixel).
__global__ void __launch_bounds__(256, 1)
deform_f2_kernel(const float* __restrict__ xpad,    // (B,64,194,194)
                 const float* __restrict__ offset,  // (B,18,192,192)
                 const float* __restrict__ wdc,     // (64,64,3,3)
                 float* __restrict__ out)           // (B,64,192,192)
{
    __shared__ __align__(16) float sW[64 * 64];  // [ci][co] for current tap

    const int b   = blockIdx.z;
    const int ty0 = blockIdx.y * 16;
    const int tx0 = blockIdx.x * 32;
    const int tid = threadIdx.x;
    const int qy  = tid >> 4, qx = tid & 15;
    const int i   = ty0 + qy;
    const int j0  = tx0 + 2 * qx;

    u64 acc[2][32];
#pragma unroll
    for (int p = 0; p < 2; p++)
#pragma unroll
        for (int j = 0; j < 32; j++) acc[p][j] = 0ull;

    for (int n = 0; n < NTAP; n++) {
        __syncthreads();
        for (int idx = tid; idx < 4096; idx += 256) {
            int ci = idx >> 6, co = idx & 63;
            sW[idx] = wdc[((size_t)co * 64 + ci) * 9 + n];
        }
        __syncthreads();

        int dr = n / 3 - 1, dc = n % 3 - 1;
        int i00[2], i11[2], i01[2], i10[2];
        float glt[2], grb[2], glb[2], grt[2];
#pragma unroll
        for (int p = 0; p < 2; p++) {
            int j = j0 + p;
            float offr = offset[(((size_t)b * 18 + n) * HH + i) * WW + j];
            float offc = offset[(((size_t)b * 18 + 9 + n) * HH + i) * WW + j];
            float p_r = (float)(i + 1 + dr) + offr;
            float p_c = (float)(j + 1 + dc) + offc;
            float pr = fminf(fmaxf(p_r, 0.f), 193.f);
            float pc = fminf(fmaxf(p_c, 0.f), 193.f);
            float fr = floorf(p_r), fc = floorf(p_c);
            float qr0 = fminf(fmaxf(fr,       0.f), 193.f);
            float qc0 = fminf(fmaxf(fc,       0.f), 193.f);
            float qr1 = fminf(fmaxf(fr + 1.f, 0.f), 193.f);
            float qc1 = fminf(fmaxf(fc + 1.f, 0.f), 193.f);
            glt[p] = (1.f + (qr0 - pr)) * (1.f + (qc0 - pc));
            grb[p] = (1.f - (qr1 - pr)) * (1.f - (qc1 - pc));
            glb[p] = (1.f + (qr0 - pr)) * (1.f - (qc1 - pc));
            grt[p] = (1.f - (qr1 - pr)) * (1.f + (qc0 - pc));
            i00[p] = (int)qr0 * HP + (int)qc0;
            i11[p] = (int)qr1 * HP + (int)qc1;
            i01[p] = (int)qr0 * HP + (int)qc1;
            i10[p] = (int)qr1 * HP + (int)qc0;
        }

        const float* xb = xpad + (size_t)b * 64 * HP * HP;
#pragma unroll 1
        for (int ci = 0; ci < 64; ci++) {
            const float* xc = xb + (size_t)ci * HP * HP;
            float xo0 = glt[0] * xc[i00[0]] + grb[0] * xc[i11[0]]
                      + glb[0] * xc[i01[0]] + grt[0] * xc[i10[0]];
            float xo1 = glt[1] * xc[i00[1]] + grb[1] * xc[i11[1]]
                      + glb[1] * xc[i01[1]] + grt[1] * xc[i10[1]];
            u64 x0 = dup2(xo0), x1 = dup2(xo1);
            const ulonglong2* wp = reinterpret_cast<const ulonglong2*>(&sW[ci * 64]);
#pragma unroll
            for (int jj = 0; jj < 16; jj++) {
                ulonglong2 q = wp[jj];
                fma2(acc[0][2 * jj],     x0, q.x);
                fma2(acc[0][2 * jj + 1], x0, q.y);
                fma2(acc[1][2 * jj],     x1, q.x);
                fma2(acc[1][2 * jj + 1], x1, q.y);
            }
        }
    }

#pragma unroll
    for (int p = 0; p < 2; p++) {
        size_t obase = (size_t)b * 64 * HH * WW + (size_t)i * WW + (j0 + p);
#pragma unroll
        for (int jj = 0; jj < 32; jj++) {
            float2 v = unpk(acc[p][jj]);
            out[obase + (size_t)(2 * jj)     * HH * WW] = v.x;
            out[obase + (size_t)(2 * jj + 1) * HH * WW] = v.y;
        }
    }
}

// ---------------- GDN + celu (in place), FFMA2 -------------------------------
__global__ void __launch_bounds__(256, 1)
gdn_celu_kernel(float* __restrict__ x, const float* __restrict__ beta,
                const float* __restrict__ gamma, int HWp)
{
    __shared__ __align__(16) float sG[64 * 64];  // sG[ci*64+co] = gamma[co][ci]
    __shared__ float sB[64];
    const int tid = threadIdx.x;
    for (int idx = tid; idx < 4096; idx += 256) {
        int co = idx & 63, ci = idx >> 6;
        sG[idx] = gamma[co * 64 + ci];
    }
    if (tid < 64) sB[tid] = beta[tid];
    __syncthreads();

    int p = blockIdx.x * 256 + tid;
    if (p >= BB * HWp) return;
    int b = p / HWp, hw = p % HWp;
    float* base = x + (size_t)b * 64 * HWp + hw;

    u64 nrm[32];
#pragma unroll
    for (int jj = 0; jj < 32; jj++) nrm[jj] = pk2(sB[2 * jj], sB[2 * jj + 1]);

    for (int ci = 0; ci < 64; ci++) {
        float v = base[(size_t)ci * HWp];
        u64 sq = dup2(v * v);
        const ulonglong2* gp = reinterpret_cast<const ulonglong2*>(&sG[ci * 64]);
#pragma unroll
        for (int jj = 0; jj < 16; jj++) {
            ulonglong2 q = gp[jj];
            fma2(nrm[2 * jj],     sq, q.x);
            fma2(nrm[2 * jj + 1], sq, q.y);
        }
    }
#pragma unroll
    for (int jj = 0; jj < 32; jj++) {
        float2 nv = unpk(nrm[jj]);
        float v0 = base[(size_t)(2 * jj) * HWp];
        float v1 = base[(size_t)(2 * jj + 1) * HWp];
        float t0 = v0 * rsqrtf(nv.x);
        float t1 = v1 * rsqrtf(nv.y);
        base[(size_t)(2 * jj) * HWp]     = (t0 > 0.f) ? t0 : expm1f(t0);
        base[(size_t)(2 * jj + 1) * HWp] = (t1 > 0.f) ? t1 : expm1f(t1);
    }
}

// ---------------- final add --------------------------------------------------
__global__ void add_kernel(const float* __restrict__ a, const float* __restrict__ b,
                           float* __restrict__ out, int n)
{
    int i = blockIdx.x * blockDim.x + threadIdx.x;
    if (i < n) out[i] = a[i] + b[i];
}

// ---------------- launcher ---------------------------------------------------
extern "C" void kernel_launch(void* const* d_in, const int* in_sizes, int n_in,
                              void* d_out, int out_size)
{
    const float* f_r     = (const float*)d_in[0];
    const float* m_t     = (const float*)d_in[1];
    const float* w_pconv = (const float*)d_in[2];
    const float* b_pconv = (const float*)d_in[3];
    const float* w_dc    = (const float*)d_in[4];
    const float* w_cat   = (const float*)d_in[5];
    const float* b_cat   = (const float*)d_in[6];
    const float* rb_w1   = (const float*)d_in[7];
    const float* rb_w2   = (const float*)d_in[8];
    const float* rb_beta = (const float*)d_in[9];
    const float* rb_gamma= (const float*)d_in[10];
    float* out = (float*)d_out;

    float *frpad, *offs, *xbuf, *ybuf, *t1;
    cudaGetSymbolAddress((void**)&frpad, g_frpad);
    cudaGetSymbolAddress((void**)&offs,  g_offset);
    cudaGetSymbolAddress((void**)&xbuf,  g_x);
    cudaGetSymbolAddress((void**)&ybuf,  g_y);
    cudaGetSymbolAddress((void**)&t1,    g_t1);

    // 1. pad f_r
    {
        int total = BB * CC * HP * HP;
        pad_kernel<<<(total + 255) / 256, 256>>>(f_r, frpad);
    }
    // 2. offset = pconv(m_t), pad 1, 64->18 (old kernel; small)
    {
        dim3 grid(12, 12, BB);
        conv3x3_kernel<64, 18, 1, false><<<grid, 256>>>(
            m_t, nullptr, w_pconv, b_pconv, nullptr, offs, HH, WW, HH, WW);
    }
    // 3. x = deform_conv(f_r, offset, w_dc)
    {
        dim3 grid(6, 12, BB);
        deform_f2_kernel<<<grid, 256>>>(frpad, offs, w_dc, xbuf);
    }
    // 4. y = conv(cat[x, f_r]), pad 1, 128->64
    {
        dim3 grid(6, 12, BB);
        conv3x3_f2_kernel<128, 1, true><<<grid, 256>>>(
            xbuf, f_r, w_cat, b_cat, nullptr, ybuf, HH, WW, HH, WW);
    }
    // 5. resblocks
    for (int l = 0; l < 3; l++) {
        const float* w1 = rb_w1 + (size_t)l * 64 * 64 * 9;
        const float* w2 = rb_w2 + (size_t)l * 64 * 64 * 9;
        const float* bt = rb_beta + (size_t)l * 64;
        const float* gm = rb_gamma + (size_t)l * 64 * 64;
        // conv1: pad 0, 192 -> 190
        {
            dim3 grid(6, 12, BB);   // ceil(190/32)=6, ceil(190/16)=12
            conv3x3_f2_kernel<64, 0, false><<<grid, 256>>>(
                ybuf, nullptr, w1, nullptr, nullptr, t1, HH, WW, 190, 190);
        }
        // gdn + celu in place on t1
        {
            int HWp = 190 * 190;
            int total = BB * HWp;
            gdn_celu_kernel<<<(total + 255) / 256, 256>>>(t1, bt, gm, HWp);
        }
        // conv2: pad 2, 190 -> 192, + residual y (in place into y)
        {
            dim3 grid(6, 12, BB);
            conv3x3_f2_kernel<64, 2, false><<<grid, 256>>>(
                t1, nullptr, w2, nullptr, ybuf, ybuf, 190, 190, HH, WW);
        }
    }
    // 6. out = y + x
    {
        int n = BB * CC * HH * WW;
        add_kernel<<<(n + 255) / 256, 256>>>(ybuf, xbuf, out, n);
    }
}

// round 4
// speedup vs baseline: 1.6181x; 1.0487x over previous
#include <cuda_runtime.h>
#include <cuda_bf16.h>
#include <math.h>

// Problem constants
#define BB 2
#define CC 64
#define HH 192
#define WW 192
#define HP 194   // padded
#define NTAP 9

typedef unsigned long long u64;

// ---------------- f32x2 packed helpers --------------------------------------
__device__ __forceinline__ u64 dup2(float x) {
    u64 r; asm("mov.b64 %0, {%1,%1};" : "=l"(r) : "f"(x)); return r;
}
__device__ __forceinline__ u64 pk2(float lo, float hi) {
    u64 r; asm("mov.b64 %0, {%1,%2};" : "=l"(r) : "f"(lo), "f"(hi)); return r;
}
__device__ __forceinline__ void fma2(u64 &d, u64 a, u64 b) {
    asm("fma.rn.f32x2 %0, %1, %2, %0;" : "+l"(d) : "l"(a), "l"(b));
}
__device__ __forceinline__ float2 unpk(u64 v) {
    float2 f; asm("mov.b64 {%0,%1}, %2;" : "=f"(f.x), "=f"(f.y) : "l"(v)); return f;
}

// ---------------- scratch buffers (static device memory; no allocation) -----
__device__ float g_frpad[BB * CC * HP * HP];
__device__ float g_offset[BB * 18 * HH * WW];
__device__ float g_x[BB * CC * HH * WW];
__device__ float g_y[BB * CC * HH * WW];
__device__ float g_t1[BB * CC * 190 * 190];

// ---------------- pad kernel -------------------------------------------------
__global__ void pad_kernel(const float* __restrict__ src, float* __restrict__ dst) {
    int idx = blockIdx.x * blockDim.x + threadIdx.x;
    int total = BB * CC * HP * HP;
    if (idx >= total) return;
    int c2 = idx % HP;
    int r2 = (idx / HP) % HP;
    int bc = idx / (HP * HP);
    float v = 0.f;
    if (r2 >= 1 && r2 <= HH && c2 >= 1 && c2 <= WW)
        v = src[(size_t)bc * HH * WW + (r2 - 1) * WW + (c2 - 1)];
    dst[idx] = v;
}

// ---------------- generic 3x3 conv (kept for pconv, COUT=18) -----------------
template<int CIN, int COUT, int PADV, bool HAS_IN2>
__global__ void __launch_bounds__(256, 1)
conv3x3_kernel(const float* __restrict__ inA, const float* __restrict__ inB,
               const float* __restrict__ w, const float* __restrict__ bias,
               const float* __restrict__ res, float* __restrict__ out,
               int Hin, int Win, int Hout, int Wout)
{
    constexpr int CH = 8;
    constexpr int COUT_P = (COUT + 3) & ~3;
    __shared__ __align__(16) float sIn[CH][18][18];
    __shared__ __align__(16) float sW[CH * 9 * COUT_P];

    const int b   = blockIdx.z;
    const int ty0 = blockIdx.y * 16;
    const int tx0 = blockIdx.x * 16;
    const int tid = threadIdx.x;
    const int py = tid >> 4, px = tid & 15;
    const int oy = ty0 + py, ox = tx0 + px;

    float acc[COUT_P];
#pragma unroll
    for (int i = 0; i < COUT_P; i++) acc[i] = 0.f;

    const int cstride = HAS_IN2 ? 64 : CIN;

    for (int c0 = 0; c0 < CIN; c0 += CH) {
        for (int idx = tid; idx < CH * 18 * 18; idx += 256) {
            int c   = idx / (18 * 18);
            int rem = idx % (18 * 18);
            int r = rem / 18, cc = rem % 18;
            int iy = ty0 - PADV + r;
            int ix = tx0 - PADV + cc;
            float v = 0.f;
            if (iy >= 0 && iy < Hin && ix >= 0 && ix < Win) {
                int ci = c0 + c;
                const float* src = inA;
                int cl = ci;
                if (HAS_IN2 && ci >= 64) { src = inB; cl = ci - 64; }
                v = src[(((size_t)b * cstride + cl) * Hin + iy) * Win + ix];
            }
            sIn[c][r][cc] = v;
        }
        for (int idx = tid; idx < CH * 9 * COUT_P; idx += 256) {
            int co = idx % COUT_P;
            int ck = idx / COUT_P;
            int ci_l = ck / 9, k = ck % 9;
            float v = 0.f;
            if (co < COUT) v = w[((size_t)co * CIN + (c0 + ci_l)) * 9 + k];
            sW[idx] = v;
        }
        __syncthreads();

        for (int ci = 0; ci < CH; ci++) {
#pragma unroll
            for (int ky = 0; ky < 3; ky++) {
#pragma unroll
                for (int kx = 0; kx < 3; kx++) {
                    float xv = sIn[ci][py + ky][px + kx];
                    const float4* wp = reinterpret_cast<const float4*>(
                        &sW[(ci * 9 + ky * 3 + kx) * COUT_P]);
#pragma unroll
                    for (int j = 0; j < COUT_P / 4; j++) {
                        float4 w4 = wp[j];
                        acc[4 * j + 0] = fmaf(w4.x, xv, acc[4 * j + 0]);
                        acc[4 * j + 1] = fmaf(w4.y, xv, acc[4 * j + 1]);
                        acc[4 * j + 2] = fmaf(w4.z, xv, acc[4 * j + 2]);
                        acc[4 * j + 3] = fmaf(w4.w, xv, acc[4 * j + 3]);
                    }
                }
            }
        }
        __syncthreads();
    }

    if (oy < Hout && ox < Wout) {
        size_t obase = (size_t)b * COUT * Hout * Wout + (size_t)oy * Wout + ox;
        size_t cs = (size_t)Hout * Wout;
#pragma unroll
        for (int co = 0; co < COUT; co++) {
            float v = acc[co];
            if (bias) v += bias[co];
            if (res)  v += res[obase + co * cs];
            out[obase + co * cs] = v;
        }
    }
}

// ---------------- FFMA2 3x3 conv, COUT=64, 512-thread / high-occupancy -------
// Block = 512 threads = 2 cout-halves x 256 threads.
// Each thread: 1x2 pixel pair x 32 output channels (16 f32x2 accs = 64 regs).
// Tile: 16 rows x 32 cols of output per block.
template<int CIN, int PADV, bool HAS_IN2>
__global__ void __launch_bounds__(512, 1)
conv3x3_f2_kernel(const float* __restrict__ inA, const float* __restrict__ inB,
                  const float* __restrict__ w, const float* __restrict__ bias,
                  const float* __restrict__ res, float* __restrict__ out,
                  int Hin, int Win, int Hout, int Wout)
{
    constexpr int CH = 8;
    __shared__ __align__(16) float sIn[CH][18][36];   // rows 18, cols 34 used (pad 36)
    __shared__ __align__(16) float sW[CH][9][64];     // [ci][tap][co]

    const int b   = blockIdx.z;
    const int ty0 = blockIdx.y * 16;
    const int tx0 = blockIdx.x * 32;
    const int tid = threadIdx.x;
    const int g   = tid >> 8;          // cout half: co base = g*32
    const int t   = tid & 255;
    const int qy  = t >> 4;            // 0..15 (output row)
    const int qx  = t & 15;            // 0..15 (output col pair)

    u64 acc[2][16];
#pragma unroll
    for (int p = 0; p < 2; p++)
#pragma unroll
        for (int j = 0; j < 16; j++) acc[p][j] = 0ull;

    const int cstride = HAS_IN2 ? 64 : CIN;

    for (int c0 = 0; c0 < CIN; c0 += CH) {
        // stage input tile
        for (int idx = tid; idx < CH * 18 * 36; idx += 512) {
            int c   = idx / 648;
            int rem = idx % 648;
            int r = rem / 36, cc = rem % 36;
            int iy = ty0 - PADV + r;
            int ix = tx0 - PADV + cc;
            float v = 0.f;
            if (cc < 34 && iy >= 0 && iy < Hin && ix >= 0 && ix < Win) {
                int ci = c0 + c;
                const float* src = inA;
                int cl = ci;
                if (HAS_IN2 && ci >= 64) { src = inB; cl = ci - 64; }
                v = src[(((size_t)b * cstride + cl) * Hin + iy) * Win + ix];
            }
            (&sIn[0][0][0])[idx] = v;
        }
        // stage weights [ci][tap][co]
        for (int idx = tid; idx < CH * 9 * 64; idx += 512) {
            int co = idx & 63;
            int ck = idx >> 6;
            int ci = ck / 9, k = ck % 9;
            (&sW[0][0][0])[idx] = w[((size_t)co * CIN + (c0 + ci)) * 9 + k];
        }
        __syncthreads();

#pragma unroll 1
        for (int ci = 0; ci < CH; ci++) {
            // 3 input rows x 4 scalars each, pre-duplicated into f32x2
            u64 d[3][4];
#pragma unroll
            for (int r = 0; r < 3; r++) {
                const float2* ip = reinterpret_cast<const float2*>(&sIn[ci][qy + r][2 * qx]);
                float2 a = ip[0], bb = ip[1];
                d[r][0] = dup2(a.x); d[r][1] = dup2(a.y);
                d[r][2] = dup2(bb.x); d[r][3] = dup2(bb.y);
            }
#pragma unroll
            for (int ky = 0; ky < 3; ky++) {
#pragma unroll
                for (int kx = 0; kx < 3; kx++) {
                    u64 xv0 = d[ky][kx];
                    u64 xv1 = d[ky][kx + 1];
                    const ulonglong2* wp = reinterpret_cast<const ulonglong2*>(
                        &sW[ci][ky * 3 + kx][g * 32]);
#pragma unroll
                    for (int j = 0; j < 8; j++) {
                        ulonglong2 q = wp[j];
                        fma2(acc[0][2 * j],     xv0, q.x);
                        fma2(acc[0][2 * j + 1], xv0, q.y);
                        fma2(acc[1][2 * j],     xv1, q.x);
                        fma2(acc[1][2 * j + 1], xv1, q.y);
                    }
                }
            }
        }
        __syncthreads();
    }

    // store
    size_t cs = (size_t)Hout * Wout;
    int oy = ty0 + qy;
#pragma unroll
    for (int pc = 0; pc < 2; pc++) {
        int ox = tx0 + 2 * qx + pc;
        if (oy < Hout && ox < Wout) {
            size_t base = (size_t)b * 64 * cs + (size_t)oy * Wout + ox;
            u64* ac = acc[pc];
#pragma unroll
            for (int j = 0; j < 16; j++) {
                float2 v = unpk(ac[j]);
                int co = g * 32 + 2 * j;
                float o0 = v.x, o1 = v.y;
                if (bias) { o0 += bias[co]; o1 += bias[co + 1]; }
                if (res)  { o0 += res[base + (size_t)co * cs];
                            o1 += res[base + (size_t)(co + 1) * cs]; }
                out[base + (size_t)co * cs]       = o0;
                out[base + (size_t)(co + 1) * cs] = o1;
            }
        }
    }
}

// ---------------- deformable conv, FFMA2, 512-thread --------------------------
// Block 512 threads, tile 16 rows x 32 cols; each thread: 1 pixel,
// all 64 couts channel-packed (32 f32x2 accs = 64 regs).
__global__ void __launch_bounds__(512, 1)
deform_f2_kernel(const float* __restrict__ xpad,    // (B,64,194,194)
                 const float* __restrict__ offset,  // (B,18,192,192)
                 const float* __restrict__ wdc,     // (64,64,3,3)
                 float* __restrict__ out)           // (B,64,192,192)
{
    __shared__ __align__(16) float sW[64 * 64];  // [ci][co] for current tap

    const int b   = blockIdx.z;
    const int ty0 = blockIdx.y * 16;
    const int tx0 = blockIdx.x * 32;
    const int tid = threadIdx.x;
    const int py  = tid >> 5, px = tid & 31;
    const int i   = ty0 + py;
    const int j   = tx0 + px;

    u64 acc[32];
#pragma unroll
    for (int c = 0; c < 32; c++) acc[c] = 0ull;

    for (int n = 0; n < NTAP; n++) {
        __syncthreads();
        for (int idx = tid; idx < 4096; idx += 512) {
            int ci = idx >> 6, co = idx & 63;
            sW[idx] = wdc[((size_t)co * 64 + ci) * 9 + n];
        }
        __syncthreads();

        int dr = n / 3 - 1, dc = n % 3 - 1;
        float offr = offset[(((size_t)b * 18 + n) * HH + i) * WW + j];
        float offc = offset[(((size_t)b * 18 + 9 + n) * HH + i) * WW + j];
        float p_r = (float)(i + 1 + dr) + offr;
        float p_c = (float)(j + 1 + dc) + offc;
        float pr = fminf(fmaxf(p_r, 0.f), 193.f);
        float pc = fminf(fmaxf(p_c, 0.f), 193.f);
        float fr = floorf(p_r), fc = floorf(p_c);
        float qr0 = fminf(fmaxf(fr,       0.f), 193.f);
        float qc0 = fminf(fmaxf(fc,       0.f), 193.f);
        float qr1 = fminf(fmaxf(fr + 1.f, 0.f), 193.f);
        float qc1 = fminf(fmaxf(fc + 1.f, 0.f), 193.f);
        float glt = (1.f + (qr0 - pr)) * (1.f + (qc0 - pc));
        float grb = (1.f - (qr1 - pr)) * (1.f - (qc1 - pc));
        float glb = (1.f + (qr0 - pr)) * (1.f - (qc1 - pc));
        float grt = (1.f - (qr1 - pr)) * (1.f + (qc0 - pc));
        int i00 = (int)qr0 * HP + (int)qc0;
        int i11 = (int)qr1 * HP + (int)qc1;
        int i01 = (int)qr0 * HP + (int)qc1;
        int i10 = (int)qr1 * HP + (int)qc0;

        const float* xb = xpad + (size_t)b * 64 * HP * HP;
#pragma unroll 1
        for (int ci = 0; ci < 64; ci++) {
            const float* xc = xb + (size_t)ci * HP * HP;
            float xo = glt * xc[i00] + grb * xc[i11]
                     + glb * xc[i01] + grt * xc[i10];
            u64 x2 = dup2(xo);
            const ulonglong2* wp = reinterpret_cast<const ulonglong2*>(&sW[ci * 64]);
#pragma unroll
            for (int jj = 0; jj < 16; jj++) {
                ulonglong2 q = wp[jj];
                fma2(acc[2 * jj],     x2, q.x);
                fma2(acc[2 * jj + 1], x2, q.y);
            }
        }
    }

    size_t obase = (size_t)b * 64 * HH * WW + (size_t)i * WW + j;
#pragma unroll
    for (int jj = 0; jj < 32; jj++) {
        float2 v = unpk(acc[jj]);
        out[obase + (size_t)(2 * jj)     * HH * WW] = v.x;
        out[obase + (size_t)(2 * jj + 1) * HH * WW] = v.y;
    }
}

// ---------------- GDN + celu (in place), FFMA2 -------------------------------
__global__ void __launch_bounds__(256, 1)
gdn_celu_kernel(float* __restrict__ x, const float* __restrict__ beta,
                const float* __restrict__ gamma, int HWp)
{
    __shared__ __align__(16) float sG[64 * 64];  // sG[ci*64+co] = gamma[co][ci]
    __shared__ float sB[64];
    const int tid = threadIdx.x;
    for (int idx = tid; idx < 4096; idx += 256) {
        int co = idx & 63, ci = idx >> 6;
        sG[idx] = gamma[co * 64 + ci];
    }
    if (tid < 64) sB[tid] = beta[tid];
    __syncthreads();

    int p = blockIdx.x * 256 + tid;
    if (p >= BB * HWp) return;
    int b = p / HWp, hw = p % HWp;
    float* base = x + (size_t)b * 64 * HWp + hw;

    u64 nrm[32];
#pragma unroll
    for (int jj = 0; jj < 32; jj++) nrm[jj] = pk2(sB[2 * jj], sB[2 * jj + 1]);

    for (int ci = 0; ci < 64; ci++) {
        float v = base[(size_t)ci * HWp];
        u64 sq = dup2(v * v);
        const ulonglong2* gp = reinterpret_cast<const ulonglong2*>(&sG[ci * 64]);
#pragma unroll
        for (int jj = 0; jj < 16; jj++) {
            ulonglong2 q = gp[jj];
            fma2(nrm[2 * jj],     sq, q.x);
            fma2(nrm[2 * jj + 1], sq, q.y);
        }
    }
#pragma unroll
    for (int jj = 0; jj < 32; jj++) {
        float2 nv = unpk(nrm[jj]);
        float v0 = base[(size_t)(2 * jj) * HWp];
        float v1 = base[(size_t)(2 * jj + 1) * HWp];
        float t0 = v0 * rsqrtf(nv.x);
        float t1 = v1 * rsqrtf(nv.y);
        base[(size_t)(2 * jj) * HWp]     = (t0 > 0.f) ? t0 : expm1f(t0);
        base[(size_t)(2 * jj + 1) * HWp] = (t1 > 0.f) ? t1 : expm1f(t1);
    }
}

// ---------------- final add --------------------------------------------------
__global__ void add_kernel(const float* __restrict__ a, const float* __restrict__ b,
                           float* __restrict__ out, int n)
{
    int i = blockIdx.x * blockDim.x + threadIdx.x;
    if (i < n) out[i] = a[i] + b[i];
}

// ---------------- launcher ---------------------------------------------------
extern "C" void kernel_launch(void* const* d_in, const int* in_sizes, int n_in,
                              void* d_out, int out_size)
{
    const float* f_r     = (const float*)d_in[0];
    const float* m_t     = (const float*)d_in[1];
    const float* w_pconv = (const float*)d_in[2];
    const float* b_pconv = (const float*)d_in[3];
    const float* w_dc    = (const float*)d_in[4];
    const float* w_cat   = (const float*)d_in[5];
    const float* b_cat   = (const float*)d_in[6];
    const float* rb_w1   = (const float*)d_in[7];
    const float* rb_w2   = (const float*)d_in[8];
    const float* rb_beta = (const float*)d_in[9];
    const float* rb_gamma= (const float*)d_in[10];
    float* out = (float*)d_out;

    float *frpad, *offs, *xbuf, *ybuf, *t1;
    cudaGetSymbolAddress((void**)&frpad, g_frpad);
    cudaGetSymbolAddress((void**)&offs,  g_offset);
    cudaGetSymbolAddress((void**)&xbuf,  g_x);
    cudaGetSymbolAddress((void**)&ybuf,  g_y);
    cudaGetSymbolAddress((void**)&t1,    g_t1);

    // 1. pad f_r
    {
        int total = BB * CC * HP * HP;
        pad_kernel<<<(total + 255) / 256, 256>>>(f_r, frpad);
    }
    // 2. offset = pconv(m_t), pad 1, 64->18
    {
        dim3 grid(12, 12, BB);
        conv3x3_kernel<64, 18, 1, false><<<grid, 256>>>(
            m_t, nullptr, w_pconv, b_pconv, nullptr, offs, HH, WW, HH, WW);
    }
    // 3. x = deform_conv(f_r, offset, w_dc)
    {
        dim3 grid(6, 12, BB);
        deform_f2_kernel<<<grid, 512>>>(frpad, offs, w_dc, xbuf);
    }
    // 4. y = conv(cat[x, f_r]), pad 1, 128->64
    {
        dim3 grid(6, 12, BB);
        conv3x3_f2_kernel<128, 1, true><<<grid, 512>>>(
            xbuf, f_r, w_cat, b_cat, nullptr, ybuf, HH, WW, HH, WW);
    }
    // 5. resblocks
    for (int l = 0; l < 3; l++) {
        const float* w1 = rb_w1 + (size_t)l * 64 * 64 * 9;
        const float* w2 = rb_w2 + (size_t)l * 64 * 64 * 9;
        const float* bt = rb_beta + (size_t)l * 64;
        const float* gm = rb_gamma + (size_t)l * 64 * 64;
        // conv1: pad 0, 192 -> 190
        {
            dim3 grid(6, 12, BB);
            conv3x3_f2_kernel<64, 0, false><<<grid, 512>>>(
                ybuf, nullptr, w1, nullptr, nullptr, t1, HH, WW, 190, 190);
        }
        // gdn + celu in place on t1
        {
            int HWp = 190 * 190;
            int total = BB * HWp;
            gdn_celu_kernel<<<(total + 255) / 256, 256>>>(t1, bt, gm, HWp);
        }
        // conv2: pad 2, 190 -> 192, + residual y (in place into y)
        {
            dim3 grid(6, 12, BB);
            conv3x3_f2_kernel<64, 2, false><<<grid, 512>>>(
                t1, nullptr, w2, nullptr, ybuf, ybuf, 190, 190, HH, WW);
        }
    }
    // 6. out = y + x
    {
        int n = BB * CC * HH * WW;
        add_kernel<<<(n + 255) / 256, 256>>>(ybuf, xbuf, out, n);
    }
}